// round 9
// baseline (speedup 1.0000x reference)
#include <cuda_runtime.h>

// Problem constants
#define TABN    1024            // table intervals over [-16, 16], h = 2^-5
#define NSTEP   32
#define NPATH   65536
#define DTC     0.03125f
#define MU_CF   0.05f
#define SIG_CF  0.2f
#define CDT     0.0015625f      // DTC * MU_CF

#define PB_TPB    64
#define PB_BLOCKS (NPATH / PB_TPB)   // 1024

// Scratch (static device globals; no runtime allocation)
__device__ float4   g_tab[TABN];          // (y_i, tanh_i, y_{i+1}, tanh_{i+1})
__device__ float2   g_part[PB_BLOCKS];    // per-block (sum ycv^2, sum yT^2)
__device__ unsigned g_ctr = 0;            // last-block ticket (reset by build)

// ---------------------------------------------------------------------------
// Kernel 1: build the y(x)/tanh(x) table (net at t=0 is a scalar function).
// Block = 512 threads = 8 table points x 64 output neurons.
// Also resets the reduction ticket counter for this graph replay.
// ---------------------------------------------------------------------------
__global__ __launch_bounds__(512) void build_kernel(
    const float* __restrict__ W1, const float* __restrict__ b1,
    const float* __restrict__ W2, const float* __restrict__ b2,
    const float* __restrict__ W3, const float* __restrict__ b3)
{
    __shared__ float sW2[64 * 64];   // 16 KB
    __shared__ float sh1[8 * 64];
    __shared__ float sred[16];

    const int tid = threadIdx.x;
    if (blockIdx.x == 0 && tid == 0) g_ctr = 0;   // reset ticket each replay

    // Stage W2 into shared memory (coalesced float4)
    {
        const float4* src = (const float4*)W2;
        float4* dst = (float4*)sW2;
        dst[tid]       = src[tid];
        dst[tid + 512] = src[tid + 512];
    }

    const int p  = tid >> 6;                 // local point 0..7
    const int j  = tid & 63;                 // output neuron 0..63
    const int pt = blockIdx.x * 8 + p;       // global table point (0..TABN + pad)
    const float x = -16.0f + (float)pt * (32.0f / (float)TABN);

    // h1_j for this point, shared within the point group
    sh1[tid] = tanhf(fmaf(x, W1[64 + j], b1[j]));
    __syncthreads();

    // a_j = b2_j + sum_k h1_k * W2[k][j]
    float a = b2[j];
    #pragma unroll
    for (int k = 0; k < 64; k++)
        a = fmaf(sh1[p * 64 + k], sW2[k * 64 + j], a);

    float contrib = tanhf(a) * W3[2 * j];

    #pragma unroll
    for (int off = 16; off > 0; off >>= 1)
        contrib += __shfl_xor_sync(0xFFFFFFFFu, contrib, off);
    if ((tid & 31) == 0) sred[tid >> 5] = contrib;
    __syncthreads();

    if (j == 0 && pt <= TABN) {
        const float y  = sred[2 * p] + sred[2 * p + 1] + b3[0];
        const float th = tanhf(x);
        float* tf = (float*)g_tab;
        if (pt < TABN) { tf[4 * pt]           = y; tf[4 * pt + 1]       = th; }
        if (pt > 0)    { tf[4 * (pt - 1) + 2] = y; tf[4 * (pt - 1) + 3] = th; }
    }
}

// ---------------------------------------------------------------------------
// Kernel 2: one thread per path, 32 tamed-Euler steps, fused final reduction.
// Tamed drift via polynomial reciprocal: mu/(1+e) ~= mu*(1-e+e^2), e<=0.025.
// x update factored to x *= (1 + sig*dw + c*s) -> short serial chain, no MUFU.
// ---------------------------------------------------------------------------
__global__ __launch_bounds__(PB_TPB) void path_kernel(
    const float* __restrict__ x0, const float* __restrict__ dW,
    float* __restrict__ out)
{
    const int b = blockIdx.x * PB_TPB + threadIdx.x;
    const float4* __restrict__ tab = g_tab;

    float x    = x0[b];
    float ylin = 1.0f;
    float acc  = 0.0f;

    const float4* dwv = (const float4*)(dW + (size_t)b * NSTEP);

    #pragma unroll
    for (int q = 0; q < NSTEP / 4; q++) {
        const float4 d4 = __ldg(&dwv[q]);
        #pragma unroll
        for (int s = 0; s < 4; s++) {
            const float dw = (s == 0) ? d4.x : (s == 1) ? d4.y : (s == 2) ? d4.z : d4.w;

            // table lookup: u = (x + 16) * 32
            float u = fmaf(x, 32.0f, 512.0f);
            u = fminf(fmaxf(u, 0.0f), 1023.999f);
            const int   i = (int)u;
            const float f = u - (float)i;
            const float4 e4 = __ldg(&tab[i]);
            const float y  = fmaf(f, e4.z - e4.x, e4.x);   // lerp y(x)
            const float th = fmaf(f, e4.w - e4.y, e4.y);   // lerp tanh(x)

            const float ycv = y - ylin;
            acc  = fmaf(ycv, ycv, acc);
            ylin = fmaf(-DTC, th, ylin);

            // tamed drift without division:
            // e = dt*|mu| = c*|x|;  1/(1+e) ~= 1 - e + e^2 = fma(e, e, 1-e)
            const float e  = CDT * fabsf(x);
            const float sc = fmaf(e, e, 1.0f - e);
            const float factor = fmaf(CDT, sc, fmaf(SIG_CF, dw, 1.0f));
            x *= factor;
        }
    }

    float yT2 = ylin * ylin;

    // Deterministic block reduction (2 warps)
    #pragma unroll
    for (int off = 16; off > 0; off >>= 1) {
        acc += __shfl_xor_sync(0xFFFFFFFFu, acc, off);
        yT2 += __shfl_xor_sync(0xFFFFFFFFu, yT2, off);
    }
    __shared__ float2 sp[PB_TPB / 32];
    __shared__ bool   s_last;
    if ((threadIdx.x & 31) == 0) sp[threadIdx.x >> 5] = make_float2(acc, yT2);
    __syncthreads();
    if (threadIdx.x == 0) {
        g_part[blockIdx.x] = make_float2(sp[0].x + sp[1].x, sp[0].y + sp[1].y);
        __threadfence();
        const unsigned t = atomicAdd(&g_ctr, 1u);
        s_last = (t == PB_BLOCKS - 1);
    }
    __syncthreads();

    // Last block performs the deterministic final reduction (fixed-order).
    if (s_last) {
        __threadfence();
        double a1 = 0.0, a2 = 0.0;
        #pragma unroll 4
        for (int k = threadIdx.x; k < PB_BLOCKS; k += PB_TPB) {
            const float2 p = g_part[k];
            a1 += (double)p.x;
            a2 += (double)p.y;
        }
        #pragma unroll
        for (int off = 16; off > 0; off >>= 1) {
            a1 += __shfl_xor_sync(0xFFFFFFFFu, a1, off);
            a2 += __shfl_xor_sync(0xFFFFFFFFu, a2, off);
        }
        __shared__ double sd[4];
        if ((threadIdx.x & 31) == 0) {
            sd[threadIdx.x >> 5]     = a1;
            sd[2 + (threadIdx.x >> 5)] = a2;
        }
        __syncthreads();
        if (threadIdx.x == 0) {
            const double s1 = sd[0] + sd[1];
            const double s2 = sd[2] + sd[3];
            const double loss = s1 / (double)((long long)NSTEP * NPATH)
                              + 0.01 * (s2 / (double)NPATH);
            out[0] = (float)loss;
        }
    }
}

// ---------------------------------------------------------------------------
// Launch: build table -> run paths (with fused reduction). Graph-capturable.
// Inputs (metadata order): x0, dW, W1, b1, W2, b2, W3, b3
// ---------------------------------------------------------------------------
extern "C" void kernel_launch(void* const* d_in, const int* in_sizes, int n_in,
                              void* d_out, int out_size)
{
    const float* x0 = (const float*)d_in[0];
    const float* dW = (const float*)d_in[1];
    const float* W1 = (const float*)d_in[2];
    const float* b1 = (const float*)d_in[3];
    const float* W2 = (const float*)d_in[4];
    const float* b2 = (const float*)d_in[5];
    const float* W3 = (const float*)d_in[6];
    const float* b3 = (const float*)d_in[7];
    (void)in_sizes; (void)n_in; (void)out_size;

    build_kernel<<<(TABN + 1 + 7) / 8, 512>>>(W1, b1, W2, b2, W3, b3);
    path_kernel<<<PB_BLOCKS, PB_TPB>>>(x0, dW, (float*)d_out);
}

// round 10
// speedup vs baseline: 1.0321x; 1.0321x over previous
#include <cuda_runtime.h>

// Problem constants
#define TABN    1024            // table intervals over [-16, 16], h = 2^-5
#define NSTEP   32
#define NPATH   65536
#define DTC     0.03125f
#define MU_CF   0.05f
#define SIG_CF  0.2f
#define CDT     0.0015625f      // DTC * MU_CF

#define PB_TPB    64
#define PB_BLOCKS (NPATH / PB_TPB)   // 1024

// Scratch (static device globals; no runtime allocation)
__device__ float4   g_tab[TABN];          // (y_i, tanh_i, y_{i+1}, tanh_{i+1})
__device__ float2   g_part[PB_BLOCKS];    // per-block (sum ycv^2, sum yT^2)
__device__ unsigned g_ctr = 0;            // last-block ticket (reset by build)

// ---------------------------------------------------------------------------
// Kernel 1: build the y(x)/tanh(x) table (net at t=0 is a scalar function).
// Block = 512 threads = 8 table points x 64 output neurons.
// Also resets the reduction ticket counter for this graph replay.
// ---------------------------------------------------------------------------
__global__ __launch_bounds__(512) void build_kernel(
    const float* __restrict__ W1, const float* __restrict__ b1,
    const float* __restrict__ W2, const float* __restrict__ b2,
    const float* __restrict__ W3, const float* __restrict__ b3)
{
    __shared__ float sW2[64 * 64];   // 16 KB
    __shared__ float sh1[8 * 64];
    __shared__ float sred[16];

    const int tid = threadIdx.x;
    if (blockIdx.x == 0 && tid == 0) g_ctr = 0;   // reset ticket each replay

    // Stage W2 into shared memory (coalesced float4)
    {
        const float4* src = (const float4*)W2;
        float4* dst = (float4*)sW2;
        dst[tid]       = src[tid];
        dst[tid + 512] = src[tid + 512];
    }

    const int p  = tid >> 6;                 // local point 0..7
    const int j  = tid & 63;                 // output neuron 0..63
    const int pt = blockIdx.x * 8 + p;       // global table point (0..TABN + pad)
    const float x = -16.0f + (float)pt * (32.0f / (float)TABN);

    // h1_j for this point, shared within the point group
    sh1[tid] = tanhf(fmaf(x, W1[64 + j], b1[j]));
    __syncthreads();

    // a_j = b2_j + sum_k h1_k * W2[k][j]
    float a = b2[j];
    #pragma unroll
    for (int k = 0; k < 64; k++)
        a = fmaf(sh1[p * 64 + k], sW2[k * 64 + j], a);

    float contrib = tanhf(a) * W3[2 * j];

    #pragma unroll
    for (int off = 16; off > 0; off >>= 1)
        contrib += __shfl_xor_sync(0xFFFFFFFFu, contrib, off);
    if ((tid & 31) == 0) sred[tid >> 5] = contrib;
    __syncthreads();

    if (j == 0 && pt <= TABN) {
        const float y  = sred[2 * p] + sred[2 * p + 1] + b3[0];
        const float th = tanhf(x);
        float* tf = (float*)g_tab;
        if (pt < TABN) { tf[4 * pt]           = y; tf[4 * pt + 1]       = th; }
        if (pt > 0)    { tf[4 * (pt - 1) + 2] = y; tf[4 * (pt - 1) + 3] = th; }
    }
}

// ---------------------------------------------------------------------------
// Kernel 2: one thread per path, 32 tamed-Euler steps, fused final reduction.
// Tamed drift via polynomial reciprocal: mu/(1+e) ~= mu*(1-e+e^2), e<=0.025.
// x update factored to x *= (1 + sig*dw + c*s) -> short serial chain, no MUFU.
// ---------------------------------------------------------------------------
__global__ __launch_bounds__(PB_TPB) void path_kernel(
    const float* __restrict__ x0, const float* __restrict__ dW,
    float* __restrict__ out)
{
    const int b = blockIdx.x * PB_TPB + threadIdx.x;
    const float4* __restrict__ tab = g_tab;

    float x    = x0[b];
    float ylin = 1.0f;
    float acc  = 0.0f;

    const float4* dwv = (const float4*)(dW + (size_t)b * NSTEP);

    #pragma unroll
    for (int q = 0; q < NSTEP / 4; q++) {
        const float4 d4 = __ldg(&dwv[q]);
        #pragma unroll
        for (int s = 0; s < 4; s++) {
            const float dw = (s == 0) ? d4.x : (s == 1) ? d4.y : (s == 2) ? d4.z : d4.w;

            // table lookup: u = (x + 16) * 32
            float u = fmaf(x, 32.0f, 512.0f);
            u = fminf(fmaxf(u, 0.0f), 1023.999f);
            const int   i = (int)u;
            const float f = u - (float)i;
            const float4 e4 = __ldg(&tab[i]);
            const float y  = fmaf(f, e4.z - e4.x, e4.x);   // lerp y(x)
            const float th = fmaf(f, e4.w - e4.y, e4.y);   // lerp tanh(x)

            const float ycv = y - ylin;
            acc  = fmaf(ycv, ycv, acc);
            ylin = fmaf(-DTC, th, ylin);

            // tamed drift without division:
            // e = dt*|mu| = c*|x|;  1/(1+e) ~= 1 - e + e^2 = fma(e, e, 1-e)
            const float e  = CDT * fabsf(x);
            const float sc = fmaf(e, e, 1.0f - e);
            const float factor = fmaf(CDT, sc, fmaf(SIG_CF, dw, 1.0f));
            x *= factor;
        }
    }

    float yT2 = ylin * ylin;

    // Deterministic block reduction (2 warps)
    #pragma unroll
    for (int off = 16; off > 0; off >>= 1) {
        acc += __shfl_xor_sync(0xFFFFFFFFu, acc, off);
        yT2 += __shfl_xor_sync(0xFFFFFFFFu, yT2, off);
    }
    __shared__ float2 sp[PB_TPB / 32];
    __shared__ bool   s_last;
    if ((threadIdx.x & 31) == 0) sp[threadIdx.x >> 5] = make_float2(acc, yT2);
    __syncthreads();
    if (threadIdx.x == 0) {
        g_part[blockIdx.x] = make_float2(sp[0].x + sp[1].x, sp[0].y + sp[1].y);
        __threadfence();
        const unsigned t = atomicAdd(&g_ctr, 1u);
        s_last = (t == PB_BLOCKS - 1);
    }
    __syncthreads();

    // Last block performs the deterministic final reduction (fixed-order).
    if (s_last) {
        __threadfence();
        double a1 = 0.0, a2 = 0.0;
        #pragma unroll 4
        for (int k = threadIdx.x; k < PB_BLOCKS; k += PB_TPB) {
            const float2 p = g_part[k];
            a1 += (double)p.x;
            a2 += (double)p.y;
        }
        #pragma unroll
        for (int off = 16; off > 0; off >>= 1) {
            a1 += __shfl_xor_sync(0xFFFFFFFFu, a1, off);
            a2 += __shfl_xor_sync(0xFFFFFFFFu, a2, off);
        }
        __shared__ double sd[4];
        if ((threadIdx.x & 31) == 0) {
            sd[threadIdx.x >> 5]     = a1;
            sd[2 + (threadIdx.x >> 5)] = a2;
        }
        __syncthreads();
        if (threadIdx.x == 0) {
            const double s1 = sd[0] + sd[1];
            const double s2 = sd[2] + sd[3];
            const double loss = s1 / (double)((long long)NSTEP * NPATH)
                              + 0.01 * (s2 / (double)NPATH);
            out[0] = (float)loss;
        }
    }
}

// ---------------------------------------------------------------------------
// Launch: build table -> run paths (with fused reduction). Graph-capturable.
// Inputs (metadata order): x0, dW, W1, b1, W2, b2, W3, b3
// ---------------------------------------------------------------------------
extern "C" void kernel_launch(void* const* d_in, const int* in_sizes, int n_in,
                              void* d_out, int out_size)
{
    const float* x0 = (const float*)d_in[0];
    const float* dW = (const float*)d_in[1];
    const float* W1 = (const float*)d_in[2];
    const float* b1 = (const float*)d_in[3];
    const float* W2 = (const float*)d_in[4];
    const float* b2 = (const float*)d_in[5];
    const float* W3 = (const float*)d_in[6];
    const float* b3 = (const float*)d_in[7];
    (void)in_sizes; (void)n_in; (void)out_size;

    build_kernel<<<(TABN + 1 + 7) / 8, 512>>>(W1, b1, W2, b2, W3, b3);
    path_kernel<<<PB_BLOCKS, PB_TPB>>>(x0, dW, (float*)d_out);
}